// round 10
// baseline (speedup 1.0000x reference)
#include <cuda_runtime.h>
#include <math.h>
#include <stdint.h>

// ---------------- problem constants (fixed shapes) ----------------
#define BB    64      // batch
#define NBLK  128     // persistent blocks; block i owns hidden dims [4i,4i+4)
#define NTHR  1024
#define KTOT  1024    // GEMM K = D + H
#define WST   1032    // SMEM weight row stride (1024 + 8 pad)
#define NKSL  8       // k-slices (128 k each)
#define RST   68      // red row stride (64 + 4)
#define RSL   1088    // red slice stride (16 rows * 68)
#define ATTN_THRESH 1e-10f

// ---------------- SMEM layout (float offsets) ----------------
#define OFF_W     0
#define SZ_W      (16*WST)              // 16512
#define OFF_RED   (OFF_W + SZ_W)
#define SZ_RED    (NKSL*RSL)            // 8704
#define OFF_ATTNA (OFF_RED + SZ_RED)
#define OFF_ATTNB (OFF_ATTNA + 1024)
#define OFF_GATES (OFF_ATTNB + 1024)    // 16 rows x 64 b
#define OFF_C     (OFF_GATES + 1024)    // 256
#define OFF_H2    (OFF_C + 256)         // 256
#define OFF_BS    (OFF_H2 + 256)        // 16
#define OFF_WSP   (OFF_BS + 16)         // 8
#define OFF_BSP   (OFF_WSP + 8)         // 2
#define OFF_SCR   (OFF_BSP + 2)         // 40 reduce scratch
#define OFF_WIN   (OFF_SCR + 40)        // 2 ints
#define SMEM_FLOATS (OFF_WIN + 4)
#define SMEM_BYTES  (SMEM_FLOATS*4)

// ---------------- persistent global state ----------------
// g_AT2: k-pair interleaved activations: (k,b) at (k>>1)*128 + b*2 + (k&1)
// k < 512 -> time_in rows, k >= 512 -> h rows.
__device__ __align__(16) float g_AT2[KTOT * BB];
__device__ float    g_spp[BB * 256];     // sp partials, batch-major [b][g*128+blk]
__device__ unsigned g_leaf[8];           // hierarchical barrier leaves
__device__ unsigned g_root;
__device__ unsigned g_gen;

// ---------------- f32x2 helpers ----------------
__device__ __forceinline__ void fma2(unsigned long long &d,
                                     unsigned long long a, unsigned long long b) {
    asm("fma.rn.f32x2 %0, %1, %2, %0;" : "+l"(d) : "l"(a), "l"(b));
}
__device__ __forceinline__ void split2(float4 w, unsigned long long &lo,
                                       unsigned long long &hi) {
    asm("mov.b64 %0, {%2, %3};\n\tmov.b64 %1, {%4, %5};"
        : "=l"(lo), "=l"(hi) : "f"(w.x), "f"(w.y), "f"(w.z), "f"(w.w));
}
__device__ __forceinline__ float hsum2(unsigned long long v) {
    float lo, hi;
    asm("mov.b64 {%0, %1}, %2;" : "=f"(lo), "=f"(hi) : "l"(v));
    return lo + hi;
}
// 16B L2-only load into two u64 (cross-SM coherent without L1 invalidation)
__device__ __forceinline__ void ldcg2(const float* p,
                                      unsigned long long &a, unsigned long long &b) {
    asm volatile("ld.global.cg.v2.u64 {%0, %1}, [%2];"
                 : "=l"(a), "=l"(b) : "l"(p));
}
__device__ __forceinline__ float ldcgf(const float* p) {
    float v;
    asm volatile("ld.global.cg.f32 %0, [%1];" : "=f"(v) : "l"(p));
    return v;
}

// ---------------- hierarchical grid barrier (128 blocks co-resident) ----------
// Release fence executed by ALL threads (each thread orders its own global
// writes to L2 before any arrival is signaled). Cross-SM data is ALWAYS read
// via ld.global.cg (L2 coherence point), so no acquire-side L1 invalidation
// is needed; x/input stays L1-resident across steps.
__device__ __forceinline__ void grid_barrier(int bi) {
    __threadfence();   // release: every thread drains its own global writes
    __syncthreads();
    if (threadIdx.x == 0) {
        unsigned gen = *(volatile unsigned*)&g_gen;
        if (atomicAdd(&g_leaf[bi & 7], 1u) == 15u) {
            if (atomicAdd(&g_root, 1u) == 7u) {
#pragma unroll
                for (int i = 0; i < 8; i++) atomicExch(&g_leaf[i], 0u);
                atomicExch(&g_root, 0u);
                __threadfence();
                atomicExch(&g_gen, gen + 1u);
            }
        }
        while (*(volatile unsigned*)&g_gen == gen) { __nanosleep(32); }
    }
    __syncthreads();
}

// ---------------- block reductions (1024 thr = 32 warps) ----------------
__device__ __forceinline__ float brsum(float v, float* scr) {
#pragma unroll
    for (int o = 16; o; o >>= 1) v += __shfl_xor_sync(0xffffffffu, v, o);
    __syncthreads();
    if ((threadIdx.x & 31) == 0) scr[threadIdx.x >> 5] = v;
    __syncthreads();
    if (threadIdx.x < 32) {
        float w = scr[threadIdx.x];
#pragma unroll
        for (int o = 16; o; o >>= 1) w += __shfl_xor_sync(0xffffffffu, w, o);
        if (threadIdx.x == 0) scr[0] = w;
    }
    __syncthreads();
    return scr[0];
}
__device__ __forceinline__ float brmax(float v, float* scr) {
#pragma unroll
    for (int o = 16; o; o >>= 1) v = fmaxf(v, __shfl_xor_sync(0xffffffffu, v, o));
    __syncthreads();
    if ((threadIdx.x & 31) == 0) scr[threadIdx.x >> 5] = v;
    __syncthreads();
    if (threadIdx.x < 32) {
        float w = scr[threadIdx.x];
#pragma unroll
        for (int o = 16; o; o >>= 1) w = fmaxf(w, __shfl_xor_sync(0xffffffffu, w, o));
        if (threadIdx.x == 0) scr[0] = w;
    }
    __syncthreads();
    return scr[0];
}

// ---------------- time_in over attn window; writes g_AT2 tin rows -------------
// x/input loads use normal LDG: read-only data, L1 persists across steps now.
__device__ __forceinline__ void compute_tin(const float* __restrict__ input,
                                            const float* __restrict__ an,
                                            float* tinred, int b, int dstart,
                                            int lo, int hi, int tid) {
    __syncthreads();
    const int dloc = tid & 255;
    const int ls   = tid >> 8;       // 0..3
    float s = 0.f;
    const float* xp = input + (size_t)b * 512 + dstart + dloc;
    for (int l = lo + ls; l <= hi; l += 4)
        s = fmaf(xp[(size_t)l * 32768], an[l], s);
    tinred[ls * 256 + dloc] = s;
    __syncthreads();
    if (tid < 256) {
        float v = tinred[tid] + tinred[256 + tid] + tinred[512 + tid] + tinred[768 + tid];
        const int k = dstart + tid;
        g_AT2[(k >> 1) * 128 + b * 2 + (k & 1)] = v;
    }
}

// ---------------- persistent kernel ----------------
__global__ void __launch_bounds__(NTHR, 1)
spacing_rnn_kernel(const float* __restrict__ input, const int* __restrict__ plen,
                   const float* __restrict__ Wih, const float* __restrict__ Whh,
                   const float* __restrict__ bih, const float* __restrict__ bhh,
                   const float* __restrict__ Wsp, const float* __restrict__ bsp,
                   float* __restrict__ out, int L)
{
    extern __shared__ float sm[];
    float* Wsm   = sm + OFF_W;
    float* red   = sm + OFF_RED;
    float* attnA = sm + OFF_ATTNA;
    float* attnB = sm + OFF_ATTNB;
    float* gates = sm + OFF_GATES;
    float* csm   = sm + OFF_C;
    float* h2s   = sm + OFF_H2;
    float* bsum  = sm + OFF_BS;
    float* wspc  = sm + OFF_WSP;
    float* bspc  = sm + OFF_BSP;
    float* scr   = sm + OFF_SCR;
    int*   win   = (int*)(sm + OFF_WIN);

    const int tid    = threadIdx.x;
    const int bi     = blockIdx.x;
    const int j0     = bi * 4;              // owned hidden dims j0..j0+3
    const int b      = bi & 63;             // phase-B batch served by this block
    const int dstart = (bi >> 6) * 256;
    int len = plen[0];
    if (len <= 0 || len > L) len = L;

    // ---------------- prologue ----------------
    for (int li = tid; li < 16 * 1024; li += NTHR) {
        int r = li >> 10, k = li & 1023;
        int gate = r >> 2, jl = r & 3;
        int grow = gate * 512 + j0 + jl;
        float w = (k < 512) ? Wih[grow * 512 + k] : Whh[grow * 512 + k - 512];
        Wsm[r * WST + k] = w;
    }
    if (tid < 16) {
        int gate = tid >> 2, jl = tid & 3;
        int grow = gate * 512 + j0 + jl;
        bsum[tid] = bih[grow] + bhh[grow];
    }
    if (tid < 8)  wspc[tid] = Wsp[(tid >> 2) * 512 + j0 + (tid & 3)];
    if (tid < 2)  bspc[tid] = bsp[tid];
    attnA[tid] = (tid == 0) ? 1.f : 0.f;
    attnB[tid] = 0.f;
    if (tid < 256) {
        csm[tid] = 0.f;
        const int k = 512 + j0 + (tid & 3);
        g_AT2[(k >> 1) * 128 + (tid >> 2) * 2 + (k & 1)] = 0.f;   // h0 = 0
    }
    __syncthreads();
    compute_tin(input, attnA, red, b, dstart, 0, 0, tid);   // tin(0) = x[:, :, 0]
    grid_barrier(bi);

    float* cur = attnA;
    float* nxt = attnB;
    int sup = 0;

    for (int t = 0; t < len; t++) {
        // ============ PHASE A: gates GEMM (f32x2, 4b x 2r x 128k) ============
        {
            const int tile = tid & 127;       // 128 tiles
            const int ks   = tid >> 7;        // 8 k-slices
            const int bt   = tile & 15;       // b-tile (4 b)
            const int rt   = tile >> 4;       // r-tile (2 rows)
            const int b0   = bt * 4;
            const int r0   = rt * 2;
            const int k0   = ks * 128;
            unsigned long long acc[2][4];
#pragma unroll
            for (int j = 0; j < 2; j++)
#pragma unroll
                for (int i = 0; i < 4; i++) acc[j][i] = 0ull;
            const float* Wb = Wsm + r0 * WST;
#pragma unroll 4
            for (int kk = 0; kk < 128; kk += 4) {
                const int k = k0 + kk;
                float4 w0f = *(const float4*)(Wb + k);
                float4 w1f = *(const float4*)(Wb + WST + k);
                const float* pa = g_AT2 + (size_t)(k >> 1) * 128 + b0 * 2;
                unsigned long long A0, A1, A2, A3, B0, B1, B2, B3;
                ldcg2(pa,       A0, A1);   // b0,b1 @ (k,k+1)
                ldcg2(pa + 4,   A2, A3);   // b2,b3 @ (k,k+1)
                ldcg2(pa + 128, B0, B1);   // b0,b1 @ (k+2,k+3)
                ldcg2(pa + 132, B2, B3);
                unsigned long long wl0, wh0, wl1, wh1;
                split2(w0f, wl0, wh0); split2(w1f, wl1, wh1);
                fma2(acc[0][0], A0, wl0); fma2(acc[0][1], A1, wl0);
                fma2(acc[0][2], A2, wl0); fma2(acc[0][3], A3, wl0);
                fma2(acc[1][0], A0, wl1); fma2(acc[1][1], A1, wl1);
                fma2(acc[1][2], A2, wl1); fma2(acc[1][3], A3, wl1);
                fma2(acc[0][0], B0, wh0); fma2(acc[0][1], B1, wh0);
                fma2(acc[0][2], B2, wh0); fma2(acc[0][3], B3, wh0);
                fma2(acc[1][0], B0, wh1); fma2(acc[1][1], B1, wh1);
                fma2(acc[1][2], B2, wh1); fma2(acc[1][3], B3, wh1);
            }
            const int base = ks * RSL + r0 * RST + b0;
            float4 v0, v1;
            v0.x = hsum2(acc[0][0]); v0.y = hsum2(acc[0][1]);
            v0.z = hsum2(acc[0][2]); v0.w = hsum2(acc[0][3]);
            v1.x = hsum2(acc[1][0]); v1.y = hsum2(acc[1][1]);
            v1.z = hsum2(acc[1][2]); v1.w = hsum2(acc[1][3]);
            *(float4*)(red + base)       = v0;
            *(float4*)(red + base + RST) = v1;
        }
        __syncthreads();
        {   // gather 8 k-slice partials -> gates[r][b]
            const int r = tid >> 6, bb2 = tid & 63;
            float s = 0.f;
#pragma unroll
            for (int ks2 = 0; ks2 < NKSL; ks2++) s += red[ks2 * RSL + r * RST + bb2];
            gates[r * 64 + bb2] = s;
        }
        __syncthreads();
        if (tid < 256) {  // LSTM cell for (b = tid>>2, jl = tid&3)
            const int bb2 = tid >> 2, jl = tid & 3;
            float gi = gates[(0  + jl) * 64 + bb2] + bsum[0  + jl];
            float gf = gates[(4  + jl) * 64 + bb2] + bsum[4  + jl];
            float gg = gates[(8  + jl) * 64 + bb2] + bsum[8  + jl];
            float go = gates[(12 + jl) * 64 + bb2] + bsum[12 + jl];
            float c  = csm[tid];
            float si = 1.f / (1.f + __expf(-gi));
            float sf = 1.f / (1.f + __expf(-gf));
            float so = 1.f / (1.f + __expf(-go));
            float c2 = sf * c + si * tanhf(gg);
            float h2 = so * tanhf(c2);
            csm[tid] = c2;
            h2s[tid] = h2;
            out[(size_t)t * 32768 + (size_t)bb2 * 512 + j0 + jl] = h2;
        }
        __syncthreads();
        if (tid < 128) {  // sp partial (batch-major store for contiguous reload)
            const int g = tid >> 6, bb2 = tid & 63;
            float s = h2s[bb2 * 4 + 0] * wspc[g * 4 + 0] + h2s[bb2 * 4 + 1] * wspc[g * 4 + 1]
                    + h2s[bb2 * 4 + 2] * wspc[g * 4 + 2] + h2s[bb2 * 4 + 3] * wspc[g * 4 + 3];
            g_spp[bb2 * 256 + g * 128 + bi] = s;
        }
        grid_barrier(bi);  // h(t-1) reads done; sp partials visible

        // ============ PHASE B: publish h, attn update, time_in ============
        if (t + 1 < len) {
            if (tid < 256) {  // publish h2 -> g_AT2 (all GEMM reads done)
                const int bb2 = tid >> 2, jl = tid & 3;
                const int k = 512 + j0 + jl;
                g_AT2[(k >> 1) * 128 + bb2 * 2 + (k & 1)] = h2s[tid];
            }
            // --- reduce sp over 128 blocks for batch b (L2-coherent reads) ---
            {
                float v = (tid < 256) ? ldcgf(g_spp + b * 256 + tid) : 0.f;
#pragma unroll
                for (int o = 16; o; o >>= 1) v += __shfl_xor_sync(0xffffffffu, v, o);
                if (tid < 256 && (tid & 31) == 0) scr[32 + (tid >> 5)] = v;  // 8 partials
                __syncthreads();
                if (tid == 0) {
                    float sp0 = scr[32] + scr[33] + scr[34] + scr[35];
                    float sp1 = scr[36] + scr[37] + scr[38] + scr[39];
                    scr[30] = 1.f / (1.f + __expf(-(sp0 + bspc[0])));
                    float pp = sp1 + bspc[1];
                    scr[31] = (pp > 0.f ? pp : 0.f) + 1.f;
                }
                __syncthreads();
            }
            const float shift = scr[30];
            const float p     = scr[31];
            const int sup2 = min(sup + 1, L - 1);
            __syncthreads();
            if (tid == 0) { win[0] = 0x7fffffff; win[1] = -1; }
            // --- attn: shift mix (exact, full support), 1 elem per thread ---
            float a2 = 0.f;
            if (tid <= sup2) {
                float a  = cur[tid];
                float ap = (tid > 0) ? cur[tid - 1] : 0.f;
                a2 = (1.f - shift) * a + shift * ap;
            }
            // --- sharpen + normalize (max-scaled pow; identical after normalize) ---
            float amax  = brmax(a2, scr);
            float lmax  = __logf(amax);
            float powed = (a2 > 0.f) ? __expf(p * (__logf(a2) - lmax)) : 0.f;
            float ssum  = brsum(powed, scr);
            float anew  = powed * (1.f / ssum);
            nxt[tid] = anew;
            if (anew >= ATTN_THRESH) { atomicMin(&win[0], tid); atomicMax(&win[1], tid); }
            __syncthreads();
            const int lo = win[0], hi = win[1];
            compute_tin(input, nxt, red, b, dstart, lo, hi, tid);
            float* tsw = cur; cur = nxt; nxt = tsw;
            sup = sup2;
            grid_barrier(bi);  // tin + h published for next phase A
        }
    }
}

extern "C" void kernel_launch(void* const* d_in, const int* in_sizes, int n_in,
                              void* d_out, int out_size) {
    const float* input = (const float*)d_in[0];
    const int*   plen  = (const int*)  d_in[1];
    const float* Wih   = (const float*)d_in[2];
    const float* Whh   = (const float*)d_in[3];
    const float* bih   = (const float*)d_in[4];
    const float* bhh   = (const float*)d_in[5];
    const float* Wsp   = (const float*)d_in[6];
    const float* bsp   = (const float*)d_in[7];
    float* out = (float*)d_out;

    int L = in_sizes[0] / (BB * 512);  // 1000

    cudaFuncSetAttribute(spacing_rnn_kernel,
                         cudaFuncAttributeMaxDynamicSharedMemorySize, SMEM_BYTES);
    spacing_rnn_kernel<<<NBLK, NTHR, SMEM_BYTES>>>(input, plen, Wih, Whh, bih, bhh,
                                                   Wsp, bsp, out, L);
}